// round 1
// baseline (speedup 1.0000x reference)
#include <cuda_runtime.h>

#define BB 64
#define DD 131072
#define KK 5
#define NT 1024

__global__ __launch_bounds__(NT, 1)
void topk5_onehot_kernel(const float* __restrict__ sim,
                         float* __restrict__ idx_out,
                         float* __restrict__ w_out) {
    __shared__ float sv[NT * KK];
    __shared__ int   si[NT * KK];

    const int b   = blockIdx.x;
    const int tid = threadIdx.x;
    const float4* row4 = reinterpret_cast<const float4*>(sim + (size_t)b * DD);

    // ---- Phase 1: per-thread top-5 over a strided slice (float4 loads) ----
    float v[KK];
    int   id[KK];
#pragma unroll
    for (int k = 0; k < KK; k++) { v[k] = -1e30f; id[k] = 0x7fffffff; }

    for (int j = tid; j < DD / 4; j += NT) {
        float4 x = row4[j];
        float xv[4] = {x.x, x.y, x.z, x.w};
        int base = j * 4;
#pragma unroll
        for (int c = 0; c < 4; c++) {
            float val = xv[c];
            if (val > v[KK - 1]) {
                v[KK - 1]  = val;
                id[KK - 1] = base + c;
#pragma unroll
                for (int q = KK - 1; q > 0; q--) {
                    if (v[q] > v[q - 1]) {
                        float tv = v[q]; v[q] = v[q - 1]; v[q - 1] = tv;
                        int   ti = id[q]; id[q] = id[q - 1]; id[q - 1] = ti;
                    }
                }
            }
        }
    }

#pragma unroll
    for (int k = 0; k < KK; k++) { sv[tid * KK + k] = v[k]; si[tid * KK + k] = id[k]; }
    __syncthreads();

    // ---- Phase 2: tree merge of sorted 5-lists ----
    for (int s = NT / 2; s > 0; s >>= 1) {
        if (tid < s) {
            float a[KK], bv[KK];
            int   ai[KK], bi[KK];
#pragma unroll
            for (int k = 0; k < KK; k++) {
                a[k]  = sv[tid * KK + k];        ai[k] = si[tid * KK + k];
                bv[k] = sv[(tid + s) * KK + k];  bi[k] = si[(tid + s) * KK + k];
            }
            int pa = 0, pb = 0;
            float m[KK]; int mi[KK];
#pragma unroll
            for (int k = 0; k < KK; k++) {
                // pa + pb == k <= 4, so both indices stay in range
                bool ta = (a[pa] > bv[pb]) || (a[pa] == bv[pb] && ai[pa] < bi[pb]);
                if (ta) { m[k] = a[pa];  mi[k] = ai[pa]; pa++; }
                else    { m[k] = bv[pb]; mi[k] = bi[pb]; pb++; }
            }
#pragma unroll
            for (int k = 0; k < KK; k++) { sv[tid * KK + k] = m[k]; si[tid * KK + k] = mi[k]; }
        }
        __syncthreads();
    }

    // Broadcast final top-5 indices (descending by value, jax.lax.top_k order)
    int fi[KK];
#pragma unroll
    for (int k = 0; k < KK; k++) fi[k] = si[k];

    // ---- Phase 3: outputs ----
    if (idx_out != nullptr && tid < KK) {
        idx_out[b * KK + tid] = (float)fi[tid];
    }

    // One-hot weight rows: soft_weights[b, k, :] = one_hot(fi[k])
#pragma unroll
    for (int k = 0; k < KK; k++) {
        float4* out4 = reinterpret_cast<float4*>(w_out + ((size_t)(b * KK + k)) * DD);
        const int sel = fi[k];
        const int sj  = sel >> 2;
        for (int j = tid; j < DD / 4; j += NT) {
            float4 z = make_float4(0.f, 0.f, 0.f, 0.f);
            if (j == sj) {
                ((float*)&z)[sel & 3] = 1.0f;
            }
            out4[j] = z;
        }
    }
}

extern "C" void kernel_launch(void* const* d_in, const int* in_sizes, int n_in,
                              void* d_out, int out_size) {
    const float* sim = (const float*)d_in[0];
    float* out = (float*)d_out;

    float* idx_out = nullptr;
    float* w_out   = out;

    const long long full = (long long)BB * KK * DD + (long long)BB * KK;
    if ((long long)out_size == full) {
        // [hard_indices (B*K floats), soft_weights (B*K*D floats)]
        idx_out = out;
        w_out   = out + BB * KK;
    }
    // else: weights only at base

    topk5_onehot_kernel<<<BB, NT>>>(sim, idx_out, w_out);
}

// round 15
// speedup vs baseline: 1.9809x; 1.9809x over previous
#include <cuda_runtime.h>

#define BB 64
#define DD 131072
#define KK 5
#define NT 1024

#define SPLIT 4
#define SEG (DD / SPLIT)        // 32768 elements per segment
#define CH 4
#define CHUNK (DD / CH)         // 32768 elements per fill chunk

__device__ float g_cand_v[BB][SPLIT * KK];
__device__ int   g_cand_i[BB][SPLIT * KK];
__device__ int   g_final[BB * KK];

// ---------------- K1: per-segment top-5 ----------------
__global__ __launch_bounds__(NT, 1)
void topk5_partial_kernel(const float* __restrict__ sim) {
    __shared__ float sv[NT * KK];
    __shared__ int   si[NT * KK];

    const int blk = blockIdx.x;          // [0, BB*SPLIT)
    const int b   = blk / SPLIT;
    const int s   = blk % SPLIT;
    const int tid = threadIdx.x;

    const float4* seg4 =
        reinterpret_cast<const float4*>(sim + (size_t)b * DD + (size_t)s * SEG);
    const int idx_base0 = s * SEG;

    float v[KK];
    int   id[KK];
#pragma unroll
    for (int k = 0; k < KK; k++) { v[k] = -1e30f; id[k] = 0x7fffffff; }
    float thresh = -1e30f;

#pragma unroll 2
    for (int j = tid; j < SEG / 4; j += NT) {
        float4 x = seg4[j];
        float xv[4] = {x.x, x.y, x.z, x.w};
        int base = idx_base0 + j * 4;
#pragma unroll
        for (int c = 0; c < 4; c++) {
            float val = xv[c];
            if (val > thresh) {
                v[KK - 1]  = val;
                id[KK - 1] = base + c;
#pragma unroll
                for (int q = KK - 1; q > 0; q--) {
                    if (v[q] > v[q - 1]) {
                        float tv = v[q]; v[q] = v[q - 1]; v[q - 1] = tv;
                        int   ti = id[q]; id[q] = id[q - 1]; id[q - 1] = ti;
                    }
                }
                thresh = v[KK - 1];
            }
        }
    }

#pragma unroll
    for (int k = 0; k < KK; k++) { sv[tid * KK + k] = v[k]; si[tid * KK + k] = id[k]; }
    __syncthreads();

    // tree merge of sorted 5-lists
    for (int st = NT / 2; st > 0; st >>= 1) {
        if (tid < st) {
            float a[KK], bv[KK];
            int   ai[KK], bi[KK];
#pragma unroll
            for (int k = 0; k < KK; k++) {
                a[k]  = sv[tid * KK + k];         ai[k] = si[tid * KK + k];
                bv[k] = sv[(tid + st) * KK + k];  bi[k] = si[(tid + st) * KK + k];
            }
            int pa = 0, pb = 0;
            float m[KK]; int mi[KK];
#pragma unroll
            for (int k = 0; k < KK; k++) {
                bool ta = (a[pa] > bv[pb]) || (a[pa] == bv[pb] && ai[pa] < bi[pb]);
                if (ta) { m[k] = a[pa];  mi[k] = ai[pa]; pa++; }
                else    { m[k] = bv[pb]; mi[k] = bi[pb]; pb++; }
            }
#pragma unroll
            for (int k = 0; k < KK; k++) { sv[tid * KK + k] = m[k]; si[tid * KK + k] = mi[k]; }
        }
        __syncthreads();
    }

    if (tid < KK) {
        g_cand_v[b][s * KK + tid] = sv[tid];
        g_cand_i[b][s * KK + tid] = si[tid];
    }
}

// ---------------- K2: merge SPLIT*KK candidates per row ----------------
__global__ __launch_bounds__(32, 1)
void topk5_merge_kernel(float* __restrict__ idx_out) {
    const int b = blockIdx.x;
    if (threadIdx.x != 0) return;

    float cv[SPLIT * KK];
    int   ci[SPLIT * KK];
#pragma unroll
    for (int j = 0; j < SPLIT * KK; j++) {
        cv[j] = g_cand_v[b][j];
        ci[j] = g_cand_i[b][j];
    }

#pragma unroll
    for (int k = 0; k < KK; k++) {
        int best = 0;
#pragma unroll
        for (int j = 1; j < SPLIT * KK; j++) {
            bool better = (cv[j] > cv[best]) ||
                          (cv[j] == cv[best] && ci[j] < ci[best]);
            if (better) best = j;
        }
        int sel = ci[best];
        g_final[b * KK + k] = sel;
        if (idx_out != nullptr) idx_out[b * KK + k] = (float)sel;
        cv[best] = -1e30f;      // remove from candidate set
        ci[best] = 0x7fffffff;
    }
}

// ---------------- K3: zero-fill weights with in-line one-hot inject ----------------
__global__ __launch_bounds__(NT, 1)
void fill_onehot_kernel(float* __restrict__ w_out) {
    const int blk   = blockIdx.x;        // [0, BB*KK*CH)
    const int r     = blk / CH;          // output row [0, BB*KK)
    const int chunk = blk % CH;
    const int tid   = threadIdx.x;

    const int sel       = g_final[r];
    const int sel_local = sel - chunk * CHUNK;   // in [0, CHUNK) if ours
    const int sj        = sel_local >> 2;
    const bool mine     = (sel_local >= 0) && (sel_local < CHUNK);

    float4* out4 = reinterpret_cast<float4*>(
        w_out + (size_t)r * DD + (size_t)chunk * CHUNK);

#pragma unroll 4
    for (int j = tid; j < CHUNK / 4; j += NT) {
        float4 z = make_float4(0.f, 0.f, 0.f, 0.f);
        if (mine && j == sj) {
            ((float*)&z)[sel_local & 3] = 1.0f;
        }
        out4[j] = z;
    }
}

extern "C" void kernel_launch(void* const* d_in, const int* in_sizes, int n_in,
                              void* d_out, int out_size) {
    const float* sim = (const float*)d_in[0];
    float* out = (float*)d_out;

    float* idx_out = nullptr;
    float* w_out   = out;

    const long long full = (long long)BB * KK * DD + (long long)BB * KK;
    if ((long long)out_size == full) {
        idx_out = out;            // [B*K] hard indices (as float)
        w_out   = out + BB * KK;  // [B*K*D] soft weights
    }

    topk5_partial_kernel<<<BB * SPLIT, NT>>>(sim);
    topk5_merge_kernel<<<BB, 32>>>(idx_out);
    fill_onehot_kernel<<<BB * KK * CH, NT>>>(w_out);
}